// round 14
// baseline (speedup 1.0000x reference)
#include <cuda_runtime.h>
#include <stdint.h>

#define NN 50000
#define NE 800000
#define IN_DIM 96
#define HID 32
#define OUT_DIM 64

// ---------------- scratch (device globals; no allocation allowed) ----------
__device__ __align__(16) float g_y1[NN * HID];    // x @ W1l (aggregated source)
__device__ __align__(16) float g_z1[NN * HID];    // x @ W1r (self term)
__device__ __align__(16) float g_h[NN * HID];     // hidden activations
__device__ __align__(16) float g_v[NN * HID];     // layer-2 mean agg (pre-scaled)
__device__ int g_deg[NN];
__device__ int g_rowptr[NN + 1];
__device__ int g_cursor[NN];
__device__ int g_srcs[NE];

// ======= gemm1 (+ fused g_deg zeroing): [y1|z1] = x @ [W1l|W1r]  (R9) =======
__global__ void __launch_bounds__(128) gemm1_kernel(
    const float* __restrict__ x,
    const float* __restrict__ W1l,
    const float* __restrict__ W1r,
    int n)
{
    __shared__ float sW[IN_DIM][2 * HID];  // 24 KB
    for (int i = threadIdx.x; i < IN_DIM * HID; i += blockDim.x) {
        int k = i / HID, j = i % HID;
        sW[k][j]       = W1l[i];
        sW[k][j + HID] = W1r[i];
    }
    __syncthreads();

    int node = blockIdx.x * blockDim.x + threadIdx.x;
    if (node >= n) return;
    g_deg[node] = 0;   // fused zeroing for hist (proven in R4)

    float acc[64];
#pragma unroll
    for (int j = 0; j < 64; j++) acc[j] = 0.f;

    const float4* xr = (const float4*)(x + (size_t)node * IN_DIM);
#pragma unroll 1
    for (int kq = 0; kq < IN_DIM / 4; kq++) {
        float4 xv = __ldg(&xr[kq]);
        float xs[4] = {xv.x, xv.y, xv.z, xv.w};
#pragma unroll
        for (int kk = 0; kk < 4; kk++) {
            float xk = xs[kk];
            const float* wr = sW[kq * 4 + kk];
#pragma unroll
            for (int j = 0; j < 64; j += 4) {
                float4 w = *(const float4*)&wr[j];
                acc[j + 0] += xk * w.x;
                acc[j + 1] += xk * w.y;
                acc[j + 2] += xk * w.z;
                acc[j + 3] += xk * w.w;
            }
        }
    }

    float* y = g_y1 + (size_t)node * HID;
    float* z = g_z1 + (size_t)node * HID;
#pragma unroll
    for (int j = 0; j < HID; j += 4) {
        *(float4*)&y[j] = make_float4(acc[j], acc[j + 1], acc[j + 2], acc[j + 3]);
        *(float4*)&z[j] = make_float4(acc[HID + j], acc[HID + j + 1],
                                      acc[HID + j + 2], acc[HID + j + 3]);
    }
}

// ================= CSR build (verified correct in R4) =======================
__global__ void hist_kernel(const int* __restrict__ dst, int E) {
    int e = blockIdx.x * blockDim.x + threadIdx.x;
    if (e < E) atomicAdd(&g_deg[dst[e]], 1);
}

#define SCAN_IT 49   // 1024 * 49 = 50176 >= NN
__global__ void __launch_bounds__(1024) scan_kernel() {
    int t = threadIdx.x;
    int lane = t & 31, warp = t >> 5;
    int base = t * SCAN_IT;

    int s = 0;
#pragma unroll 1
    for (int j = 0; j < SCAN_IT; j++) {
        int idx = base + j;
        if (idx < NN) s += g_deg[idx];
    }
    int incl = s;
#pragma unroll
    for (int o = 1; o < 32; o <<= 1) {
        int v = __shfl_up_sync(~0u, incl, o);
        if (lane >= o) incl += v;
    }
    __shared__ int wtot[32];
    if (lane == 31) wtot[warp] = incl;
    __syncthreads();
    if (warp == 0) {
        int v = wtot[lane];
        int iv = v;
#pragma unroll
        for (int o = 1; o < 32; o <<= 1) {
            int u = __shfl_up_sync(~0u, iv, o);
            if (lane >= o) iv += u;
        }
        wtot[lane] = iv - v;
    }
    __syncthreads();

    int run = wtot[warp] + incl - s;
#pragma unroll 1
    for (int j = 0; j < SCAN_IT; j++) {
        int idx = base + j;
        if (idx < NN) {
            g_rowptr[idx] = run;
            g_cursor[idx] = run;
            run += g_deg[idx];
        }
    }
    if (t == 1023) g_rowptr[NN] = run;
}

__global__ void fill_kernel(const int* __restrict__ ei, int E) {
    int e = blockIdx.x * blockDim.x + threadIdx.x;
    if (e >= E) return;
    int src = ei[e];
    int dst = ei[E + e];
    int pos = atomicAdd(&g_cursor[dst], 1);
    g_srcs[pos] = src;
}

// ====== gather layer 1 (fused combine+relu): warp/node, MLP=4, no shfl ======
// lane = feature. All lanes load the same srcs[i] -> L1 broadcast. 4 separate
// accumulators keep 4 independent idx->feat load chains in flight.
__global__ void __launch_bounds__(256) gather1_kernel(const float* __restrict__ b1) {
    int gtid = blockIdx.x * blockDim.x + threadIdx.x;
    int node = gtid >> 5;
    int lane = gtid & 31;
    if (node >= NN) return;

    int rs = g_rowptr[node];
    int re = g_rowptr[node + 1];

    float a0 = 0.f, a1 = 0.f, a2 = 0.f, a3 = 0.f;
    int i = rs;
#pragma unroll 1
    for (; i + 4 <= re; i += 4) {
        int s0 = __ldg(&g_srcs[i + 0]);
        int s1 = __ldg(&g_srcs[i + 1]);
        int s2 = __ldg(&g_srcs[i + 2]);
        int s3 = __ldg(&g_srcs[i + 3]);
        a0 += __ldg(&g_y1[(size_t)s0 * HID + lane]);
        a1 += __ldg(&g_y1[(size_t)s1 * HID + lane]);
        a2 += __ldg(&g_y1[(size_t)s2 * HID + lane]);
        a3 += __ldg(&g_y1[(size_t)s3 * HID + lane]);
    }
#pragma unroll 1
    for (; i < re; i++) {
        int s = __ldg(&g_srcs[i]);
        a0 += __ldg(&g_y1[(size_t)s * HID + lane]);
    }
    float acc = (a0 + a1) + (a2 + a3);

    float invc = 1.0f / fmaxf((float)(re - rs), 1.0f);
    float hval = fmaxf(
        fmaf(acc, invc, g_z1[(size_t)node * HID + lane] + __ldg(&b1[lane])), 0.f);
    g_h[(size_t)node * HID + lane] = hval;
}

// ================= gather layer 2 (writes pre-scaled mean) ==================
__global__ void __launch_bounds__(256) gather2_kernel() {
    int gtid = blockIdx.x * blockDim.x + threadIdx.x;
    int node = gtid >> 5;
    int lane = gtid & 31;
    if (node >= NN) return;

    int rs = g_rowptr[node];
    int re = g_rowptr[node + 1];

    float a0 = 0.f, a1 = 0.f, a2 = 0.f, a3 = 0.f;
    int i = rs;
#pragma unroll 1
    for (; i + 4 <= re; i += 4) {
        int s0 = __ldg(&g_srcs[i + 0]);
        int s1 = __ldg(&g_srcs[i + 1]);
        int s2 = __ldg(&g_srcs[i + 2]);
        int s3 = __ldg(&g_srcs[i + 3]);
        a0 += __ldg(&g_h[(size_t)s0 * HID + lane]);
        a1 += __ldg(&g_h[(size_t)s1 * HID + lane]);
        a2 += __ldg(&g_h[(size_t)s2 * HID + lane]);
        a3 += __ldg(&g_h[(size_t)s3 * HID + lane]);
    }
#pragma unroll 1
    for (; i < re; i++) {
        int s = __ldg(&g_srcs[i]);
        a0 += __ldg(&g_h[(size_t)s * HID + lane]);
    }
    float acc = (a0 + a1) + (a2 + a3);

    float invc = 1.0f / fmaxf((float)(re - rs), 1.0f);
    g_v[(size_t)node * HID + lane] = acc * invc;
}

// ================= layer 2: out = v@W2l + h@W2r + b2 (R3-proven) ============
__global__ void __launch_bounds__(128) layer2_kernel(
    const float* __restrict__ W2l,
    const float* __restrict__ W2r,
    const float* __restrict__ b2,
    float* __restrict__ out,
    int n)
{
    __shared__ float sW[2 * HID][OUT_DIM];  // 16 KB; rows 0..31 = W2l
    for (int i = threadIdx.x; i < HID * OUT_DIM; i += blockDim.x) {
        int k = i / OUT_DIM, j = i % OUT_DIM;
        sW[k][j]       = W2l[i];
        sW[k + HID][j] = W2r[i];
    }
    __syncthreads();

    int node = blockIdx.x * blockDim.x + threadIdx.x;
    if (node >= n) return;

    float v[64];
#pragma unroll
    for (int k = 0; k < HID; k += 4) {
        float4 a = *(const float4*)&g_v[(size_t)node * HID + k];
        v[k + 0] = a.x; v[k + 1] = a.y; v[k + 2] = a.z; v[k + 3] = a.w;
        float4 hh = *(const float4*)&g_h[(size_t)node * HID + k];
        v[HID + k + 0] = hh.x; v[HID + k + 1] = hh.y;
        v[HID + k + 2] = hh.z; v[HID + k + 3] = hh.w;
    }

#pragma unroll 1
    for (int j = 0; j < OUT_DIM; j += 4) {
        float4 bb = *(const float4*)&b2[j];
        float a0 = bb.x, a1 = bb.y, a2 = bb.z, a3 = bb.w;
#pragma unroll
        for (int k = 0; k < 64; k++) {
            float4 w = *(const float4*)&sW[k][j];
            a0 += v[k] * w.x;
            a1 += v[k] * w.y;
            a2 += v[k] * w.z;
            a3 += v[k] * w.w;
        }
        *(float4*)&out[(size_t)node * OUT_DIM + j] = make_float4(a0, a1, a2, a3);
    }
}

// ================= launch ===================================================
extern "C" void kernel_launch(void* const* d_in, const int* in_sizes, int n_in,
                              void* d_out, int out_size)
{
    const float* x   = (const float*)d_in[0];
    const int*   ei  = (const int*)d_in[1];   // int32 (JAX x64 disabled)
    const float* W1l = (const float*)d_in[2];
    const float* W1r = (const float*)d_in[3];
    const float* b1  = (const float*)d_in[4];
    const float* W2l = (const float*)d_in[5];
    const float* W2r = (const float*)d_in[6];
    const float* b2  = (const float*)d_in[7];
    float*       out = (float*)d_out;

    int n = in_sizes[0] / IN_DIM;   // 50000
    int E = in_sizes[1] / 2;        // 800000

    // 1) layer-1 GEMM (also zeroes g_deg for the histogram)
    gemm1_kernel<<<(n + 127) / 128, 128>>>(x, W1l, W1r, n);
    // 2-4) CSR build (no atomic-fp32 anywhere after this point)
    hist_kernel<<<(E + 511) / 512, 512>>>(ei + E, E);
    scan_kernel<<<1, 1024>>>();
    fill_kernel<<<(E + 511) / 512, 512>>>(ei, E);
    // 5) gather + combine + relu -> h   (replaces scatter1 + combine1 + zero)
    {
        long long work = (long long)NN * 32;
        gather1_kernel<<<(int)((work + 255) / 256), 256>>>(b1);
    }
    // 6) gather -> v (pre-scaled mean)   (replaces scatter2)
    {
        long long work = (long long)NN * 32;
        gather2_kernel<<<(int)((work + 255) / 256), 256>>>();
    }
    // 7) output GEMV
    layer2_kernel<<<(n + 127) / 128, 128>>>(W2l, W2r, b2, out, n);
}

// round 15
// speedup vs baseline: 1.7818x; 1.7818x over previous
#include <cuda_runtime.h>
#include <stdint.h>

#define NN 50000
#define NE 800000
#define IN_DIM 96
#define HID 32
#define OUT_DIM 64
#define EPT 4   // edges per thread in scatter (MLP)

#define G1_BS 128          // gemm1 block size = nodes per block
#define XPITCH 97          // smem row pitch in floats (97 mod 32 == 1 -> no conflicts)
#define G1_SMEM ((IN_DIM * 2 * HID + G1_BS * XPITCH) * 4)  // 24576 + 49664 = 74240 B

// ---------------- scratch (device globals; no allocation allowed) ----------
__device__ __align__(16) float g_y1[NN * HID];    // x @ W1l   (to be aggregated)
__device__ __align__(16) float g_z1[NN * HID];    // x @ W1r   (self term)
__device__ __align__(16) float g_agg1[NN * HID];  // scatter accum, layer 1
__device__ __align__(16) float g_h[NN * HID];     // hidden activations
__device__ __align__(16) float g_agg2[NN * HID];  // scatter accum, layer 2
__device__ float g_cnt[NN];
__device__ float g_invc[NN];

// ---------------- zero the accumulators (coalesced, proven) ----------------
__global__ void zero_bufs() {
    int i = blockIdx.x * blockDim.x + threadIdx.x;
    const int nv4 = NN * HID / 4;
    if (i < nv4) {
        ((float4*)g_agg1)[i] = make_float4(0.f, 0.f, 0.f, 0.f);
        ((float4*)g_agg2)[i] = make_float4(0.f, 0.f, 0.f, 0.f);
    }
    if (i < NN) g_cnt[i] = 0.f;
}

// -------- gemm1: [y1 | z1] = x @ [W1l | W1r], smem-staged x tile -----------
// Block coop-loads its 128 node rows of x coalesced into smem (high MLP,
// bandwidth-bound), then computes from smem. Kills the 24-deep serial LDG
// chain that latency-bound the R9 version.
__global__ void __launch_bounds__(G1_BS) gemm1_kernel(
    const float* __restrict__ x,
    const float* __restrict__ W1l,
    const float* __restrict__ W1r,
    int n)
{
    extern __shared__ float smem[];
    float* sW = smem;                            // [IN_DIM][2*HID] = 6144 floats
    float* sX = smem + IN_DIM * 2 * HID;         // [G1_BS][XPITCH]

    // load weights (coalesced)
    for (int i = threadIdx.x; i < IN_DIM * HID; i += G1_BS) {
        int k = i / HID, j = i % HID;
        sW[k * 2 * HID + j]       = W1l[i];
        sW[k * 2 * HID + j + HID] = W1r[i];
    }

    // coop-load x tile: 128 rows x 96 floats, coalesced float4 stream.
    int base = blockIdx.x * G1_BS;               // first node of this block
    const int nf4 = G1_BS * IN_DIM / 4;          // 3072 float4s
#pragma unroll
    for (int i = threadIdx.x; i < nf4; i += G1_BS) {
        int lrow = (i * 4) / IN_DIM;             // local node row
        int lcol = (i * 4) % IN_DIM;
        float4 v = make_float4(0.f, 0.f, 0.f, 0.f);
        if (base + lrow < n)
            v = __ldg((const float4*)(x + (size_t)(base + lrow) * IN_DIM + lcol));
        float* d = &sX[lrow * XPITCH + lcol];    // pitch 97: scalar stores
        d[0] = v.x; d[1] = v.y; d[2] = v.z; d[3] = v.w;
    }
    __syncthreads();

    int node = base + threadIdx.x;
    if (node >= n) return;

    float acc[64];
#pragma unroll
    for (int j = 0; j < 64; j++) acc[j] = 0.f;

    const float* xrow = &sX[threadIdx.x * XPITCH];
#pragma unroll 1
    for (int kq = 0; kq < IN_DIM / 4; kq++) {
        float xs[4];
#pragma unroll
        for (int i = 0; i < 4; i++) xs[i] = xrow[kq * 4 + i];
#pragma unroll
        for (int kk = 0; kk < 4; kk++) {
            float xk = xs[kk];
            const float* wr = &sW[(kq * 4 + kk) * 2 * HID];
#pragma unroll
            for (int j = 0; j < 64; j += 4) {
                float4 w = *(const float4*)&wr[j];
                acc[j + 0] += xk * w.x;
                acc[j + 1] += xk * w.y;
                acc[j + 2] += xk * w.z;
                acc[j + 3] += xk * w.w;
            }
        }
    }

    float* y = g_y1 + (size_t)node * HID;
    float* z = g_z1 + (size_t)node * HID;
#pragma unroll
    for (int j = 0; j < HID; j += 4) {
        *(float4*)&y[j] = make_float4(acc[j], acc[j + 1], acc[j + 2], acc[j + 3]);
        *(float4*)&z[j] = make_float4(acc[HID + j], acc[HID + j + 1],
                                      acc[HID + j + 2], acc[HID + j + 3]);
    }
}

// ---------------- edge scatter: agg[dst] += feat[src] (dim 32) -------------
// (byte-identical to R9: 8 lanes/edge, EPT independent edges per thread)
__global__ void __launch_bounds__(256) scatter_kernel(
    const int* __restrict__ ei, int E, int layer)
{
    int tid = blockIdx.x * blockDim.x + threadIdx.x;
    int g = tid >> 3;           // edge-group id
    int l = tid & 7;            // lane within edge (feature quad)
    int G = (E + EPT - 1) / EPT;
    if (g >= G) return;

    const float* feat = (layer == 0) ? g_y1 : g_h;
    float*       agg  = (layer == 0) ? g_agg1 : g_agg2;

    int  e[EPT];
    bool valid[EPT];
    int  src[EPT], dst[EPT];
#pragma unroll
    for (int k = 0; k < EPT; k++) {
        e[k] = g + k * G;
        valid[k] = (e[k] < E);
    }
#pragma unroll
    for (int k = 0; k < EPT; k++) {
        if (valid[k]) {
            src[k] = __ldg(&ei[e[k]]);
            dst[k] = __ldg(&ei[E + e[k]]);
        }
    }
    float4 v[EPT];
#pragma unroll
    for (int k = 0; k < EPT; k++) {
        if (valid[k])
            v[k] = *(const float4*)(feat + (size_t)src[k] * HID + l * 4);
    }
#pragma unroll
    for (int k = 0; k < EPT; k++) {
        if (valid[k]) {
            float* p = agg + (size_t)dst[k] * HID + l * 4;
            asm volatile("red.global.add.v4.f32 [%0], {%1,%2,%3,%4};"
                         :: "l"(p), "f"(v[k].x), "f"(v[k].y), "f"(v[k].z), "f"(v[k].w)
                         : "memory");
            if (layer == 0 && l == 0) atomicAdd(g_cnt + dst[k], 1.0f);
        }
    }
}

// ---------------- combine layer 1: h = relu(agg1/cnt + z1 + b1) ------------
__global__ void combine1_kernel(const float* __restrict__ b1, int n) {
    int tid = blockIdx.x * blockDim.x + threadIdx.x;
    int node = tid >> 3;
    int q = tid & 7;
    if (node >= n) return;

    float c = g_cnt[node];
    float invc = 1.0f / fmaxf(c, 1.0f);
    if (q == 0) g_invc[node] = invc;

    size_t off = (size_t)node * HID + q * 4;
    float4 a  = *(const float4*)&g_agg1[off];
    float4 z  = *(const float4*)&g_z1[off];
    float4 bb = *(const float4*)&b1[q * 4];
    float4 h;
    h.x = fmaxf(fmaf(a.x, invc, z.x + bb.x), 0.f);
    h.y = fmaxf(fmaf(a.y, invc, z.y + bb.y), 0.f);
    h.z = fmaxf(fmaf(a.z, invc, z.z + bb.z), 0.f);
    h.w = fmaxf(fmaf(a.w, invc, z.w + bb.w), 0.f);
    *(float4*)&g_h[off] = h;
}

// ---------------- layer 2: out = (agg2/cnt)@W2l + h@W2r + b2 (R9) ----------
__global__ void __launch_bounds__(128) layer2_kernel(
    const float* __restrict__ W2l,
    const float* __restrict__ W2r,
    const float* __restrict__ b2,
    float* __restrict__ out,
    int n)
{
    __shared__ float sW[2 * HID][OUT_DIM];  // 16 KB; rows 0..31 = W2l
    for (int i = threadIdx.x; i < HID * OUT_DIM; i += blockDim.x) {
        int k = i / OUT_DIM, j = i % OUT_DIM;
        sW[k][j]       = W2l[i];
        sW[k + HID][j] = W2r[i];
    }
    __syncthreads();

    int node = blockIdx.x * blockDim.x + threadIdx.x;
    if (node >= n) return;

    float invc = g_invc[node];
    float v[64];
#pragma unroll
    for (int k = 0; k < HID; k += 4) {
        float4 a = *(const float4*)&g_agg2[(size_t)node * HID + k];
        v[k + 0] = a.x * invc;
        v[k + 1] = a.y * invc;
        v[k + 2] = a.z * invc;
        v[k + 3] = a.w * invc;
        float4 hh = *(const float4*)&g_h[(size_t)node * HID + k];
        v[HID + k + 0] = hh.x;
        v[HID + k + 1] = hh.y;
        v[HID + k + 2] = hh.z;
        v[HID + k + 3] = hh.w;
    }

#pragma unroll 1
    for (int j = 0; j < OUT_DIM; j += 4) {
        float4 bb = *(const float4*)&b2[j];
        float a0 = bb.x, a1 = bb.y, a2 = bb.z, a3 = bb.w;
#pragma unroll
        for (int k = 0; k < 64; k++) {
            float4 w = *(const float4*)&sW[k][j];
            a0 += v[k] * w.x;
            a1 += v[k] * w.y;
            a2 += v[k] * w.z;
            a3 += v[k] * w.w;
        }
        *(float4*)&out[(size_t)node * OUT_DIM + j] = make_float4(a0, a1, a2, a3);
    }
}

// ---------------- launch --------------------------------------------------
extern "C" void kernel_launch(void* const* d_in, const int* in_sizes, int n_in,
                              void* d_out, int out_size)
{
    const float* x   = (const float*)d_in[0];
    const int*   ei  = (const int*)d_in[1];   // int32 (JAX x64 disabled)
    const float* W1l = (const float*)d_in[2];
    const float* W1r = (const float*)d_in[3];
    const float* b1  = (const float*)d_in[4];
    const float* W2l = (const float*)d_in[5];
    const float* W2r = (const float*)d_in[6];
    const float* b2  = (const float*)d_in[7];
    float*       out = (float*)d_out;

    int n = in_sizes[0] / IN_DIM;   // 50000
    int E = in_sizes[1] / 2;        // 800000

    // allow 72.5 KB dynamic smem for gemm1 (attribute set, not an allocation;
    // idempotent, called every launch)
    cudaFuncSetAttribute(gemm1_kernel,
                         cudaFuncAttributeMaxDynamicSharedMemorySize, G1_SMEM);

    // 1) zero accumulators + counts
    {
        int tot = NN * HID / 4;
        zero_bufs<<<(tot + 255) / 256, 256>>>();
    }
    // 2) [y1|z1] = x @ [W1l|W1r], smem-staged
    gemm1_kernel<<<(n + G1_BS - 1) / G1_BS, G1_BS, G1_SMEM>>>(x, W1l, W1r, n);
    // 3) scatter y1 into agg1 (+ degree counts)
    {
        int G = (E + EPT - 1) / EPT;
        long long work = (long long)G * 8;
        scatter_kernel<<<(int)((work + 255) / 256), 256>>>(ei, E, 0);
    }
    // 4) h = relu(agg1/cnt + z1 + b1)
    combine1_kernel<<<(n * 8 + 255) / 256, 256>>>(b1, n);
    // 5) scatter h into agg2
    {
        int G = (E + EPT - 1) / EPT;
        long long work = (long long)G * 8;
        scatter_kernel<<<(int)((work + 255) / 256), 256>>>(ei, E, 1);
    }
    // 6) out = (agg2/cnt)@W2l + h@W2r + b2
    layer2_kernel<<<(n + 127) / 128, 128>>>(W2l, W2r, b2, out, n);
}